// round 14
// baseline (speedup 1.0000x reference)
#include <cuda_runtime.h>
#include <cuda_bf16.h>
#include <math.h>

#define T_STEPS 16384
#define N_DIM   256
#define M_DIM   512
#define G3      1536   // 3*M
#define NADDR   512    // K_MEM+1
#define L_OUT   256

#define CSZ     16     // cluster size (CTAs)
#define DPC     32     // h-dims per CTA (512/16)
#define NTHR    512

// ---------------- device scratch (static, no allocation) ----------------
__device__ __align__(16) float  d_Gi[T_STEPS * G3];      // X @ W_ih^T + b_ih
__device__ __align__(16) float  d_H [T_STEPS * M_DIM];   // h_out history
__device__ __align__(16) float  d_M [NADDR * M_DIM];     // memory rows (write-once)
__device__ __align__(16) float4 d_Gc4[NADDR * M_DIM];    // cache: (gr,gz,gn,hp) per [q][dim]
__device__ int d_dec[T_STEPS];                           // per-step memory-read record

// ---------------- helpers ----------------
__device__ __forceinline__ void stasync_u64(unsigned long long* lptr, unsigned long long* lmbar,
                                            unsigned rank, unsigned long long v) {
    unsigned la = (unsigned)__cvta_generic_to_shared(lptr);
    unsigned lm = (unsigned)__cvta_generic_to_shared(lmbar);
    unsigned ra, rm;
    asm volatile("mapa.shared::cluster.u32 %0, %1, %2;" : "=r"(ra) : "r"(la), "r"(rank));
    asm volatile("mapa.shared::cluster.u32 %0, %1, %2;" : "=r"(rm) : "r"(lm), "r"(rank));
    asm volatile("st.async.weak.shared::cluster.mbarrier::complete_tx::bytes.b64 [%0], %1, [%2];"
                 :: "r"(ra), "l"(v), "r"(rm) : "memory");
}
__device__ __forceinline__ void bulk_s2s(float* ldst, const float* lsrc,
                                         unsigned long long* lmbar,
                                         unsigned rank, unsigned bytes) {
    unsigned ld = (unsigned)__cvta_generic_to_shared(ldst);
    unsigned ls = (unsigned)__cvta_generic_to_shared(lsrc);
    unsigned lm = (unsigned)__cvta_generic_to_shared(lmbar);
    unsigned rd, rm;
    asm volatile("mapa.shared::cluster.u32 %0, %1, %2;" : "=r"(rd) : "r"(ld), "r"(rank));
    asm volatile("mapa.shared::cluster.u32 %0, %1, %2;" : "=r"(rm) : "r"(lm), "r"(rank));
    asm volatile("cp.async.bulk.shared::cluster.shared::cta.mbarrier::complete_tx::bytes "
                 "[%0], [%1], %2, [%3];"
                 :: "r"(rd), "r"(ls), "r"(bytes), "r"(rm) : "memory");
}
__device__ __forceinline__ void mbar_init(unsigned long long* m, unsigned cnt) {
    unsigned a = (unsigned)__cvta_generic_to_shared(m);
    asm volatile("mbarrier.init.shared.b64 [%0], %1;" :: "r"(a), "r"(cnt) : "memory");
}
__device__ __forceinline__ void mbar_expect_tx(unsigned long long* m, unsigned bytes) {
    unsigned a = (unsigned)__cvta_generic_to_shared(m);
    asm volatile("mbarrier.arrive.expect_tx.shared.b64 _, [%0], %1;" :: "r"(a), "r"(bytes) : "memory");
}
__device__ __forceinline__ void mbar_wait(unsigned long long* m, unsigned parity) {
    unsigned a = (unsigned)__cvta_generic_to_shared(m);
    unsigned done;
    asm volatile("{\n\t.reg .pred p;\n\t"
                 "mbarrier.try_wait.parity.acquire.cta.shared::cta.b64 p, [%1], %2;\n\t"
                 "selp.b32 %0, 1, 0, p;\n\t}"
                 : "=r"(done) : "r"(a), "r"(parity) : "memory");
    if (!done) {
        asm volatile("{\n\t.reg .pred P1;\n\t"
                     "WL_%=:\n\t"
                     "mbarrier.try_wait.parity.acquire.cta.shared::cta.b64 P1, [%0], %1, 0x989680;\n\t"
                     "@P1 bra.uni WD_%=;\n\t"
                     "bra.uni WL_%=;\n\t"
                     "WD_%=:\n\t}"
                     :: "r"(a), "r"(parity) : "memory");
    }
}
#define CLUSTER_SYNC() do { \
    asm volatile("barrier.cluster.arrive.aligned;" ::: "memory"); \
    asm volatile("barrier.cluster.wait.aligned;"   ::: "memory"); } while (0)

__device__ __forceinline__ unsigned long long warp_max_key(unsigned long long k) {
    unsigned hi = (unsigned)(k >> 32);
    unsigned lo = (unsigned)k;
    unsigned mhi = __reduce_max_sync(0xFFFFFFFFu, hi);
    unsigned mlo = __reduce_max_sync(0xFFFFFFFFu, (hi == mhi) ? lo : 0u);
    return ((unsigned long long)mhi << 32) | mlo;
}

// ---------------- textbook 32x32 tiled NT GEMM (known good) ----------------
__global__ __launch_bounds__(1024) void gemm32_nt(
    const float* __restrict__ A, const float* __restrict__ B,
    const float* __restrict__ bias, float* __restrict__ C,
    int M, int N, int K)
{
    __shared__ float As[32][33];
    __shared__ float Bs[32][33];
    const int bm = blockIdx.y * 32;
    const int bn = blockIdx.x * 32;
    const int tx = threadIdx.x;
    const int ty = threadIdx.y;
    float acc = 0.f;
    for (int k0 = 0; k0 < K; k0 += 32) {
        As[ty][tx] = A[(size_t)(bm + ty) * K + k0 + tx];
        Bs[ty][tx] = B[(size_t)(bn + ty) * K + k0 + tx];
        __syncthreads();
        #pragma unroll
        for (int k = 0; k < 32; k++)
            acc = fmaf(As[ty][k], Bs[tx][k], acc);
        __syncthreads();
    }
    C[(size_t)(bm + ty) * N + bn + tx] = acc + bias[bn + tx];
}

// ---------------- post-pass: fill d_H rows recorded as memory reads ----------------
__global__ __launch_bounds__(M_DIM) void dmm_fixup(void) {
    const int t = blockIdx.x;
    const int q = d_dec[t];
    if (q >= 0)
        d_H[(size_t)t * M_DIM + threadIdx.x] = d_M[(size_t)q * M_DIM + threadIdx.x];
}

// ---------------- clustered recurrent kernel (warp-0 serial section) ----------------
// Warp 0 lane j owns dim 32c+j: decision -> coalesced cache load -> gates ->
// stage -> syncwarp -> bulk issue, all intra-warp. Warps 1-15 only do logits
// (+ rare spec GEMV, staged to warp 0 via spec_sm). Arithmetic verbatim ->
// trajectory bit-identical to rounds 4..13.
__global__ __launch_bounds__(NTHR, 1) void dmm_rec(
    const float* __restrict__ h0,
    const float* __restrict__ W_hh,
    const float* __restrict__ b_hh,
    const float* __restrict__ C_w,
    const float* __restrict__ C_b)
{
    extern __shared__ float W_sm[];                 // [2*DPC][512]: z rows, n rows
    __shared__ __align__(16) float hn_sm[2][M_DIM];
    __shared__ __align__(16) float stage_sm[2][DPC];
    __shared__ __align__(16) float4 spec_sm[DPC];   // spec results -> warp 0
    __shared__ unsigned long long wkey_sm[16];
    __shared__ unsigned long long ckey_sm[CSZ];
    __shared__ unsigned char written_w[16][NADDR];
    __shared__ unsigned long long mbar_hn, mbar_key;

    const int c   = blockIdx.x;
    const int tid = threadIdx.x;
    const int w   = tid >> 5;
    const int l   = tid & 31;
    const int d0  = DPC * c + w;
    const int d1  = DPC * c + 16 + w;
    const int dj  = DPC * c + l;                    // warp-0 lane dim

    for (int idx = tid; idx < 2 * DPC * M_DIM; idx += NTHR) {
        int g   = idx >> 14;
        int rem = idx & 16383;
        int lr  = rem >> 9;
        int col = rem & 511;
        W_sm[idx] = W_hh[(size_t)((g + 1) * M_DIM + DPC * c + lr) * M_DIM + col];
    }
    for (int idx = tid; idx < 16 * NADDR; idx += NTHR)
        written_w[idx >> 9][idx & 511] = 0;
    if (tid == 0) {
        mbar_init(&mbar_hn, 1);
        mbar_init(&mbar_key, 1);
        asm volatile("fence.mbarrier_init.release.cluster;" ::: "memory");
    }

    float4 wr0[4], wr1[4], cw0[4], cw1[4];
    #pragma unroll
    for (int cch = 0; cch < 4; cch++) {
        wr0[cch] = *(const float4*)&W_hh[(size_t)d0 * M_DIM + cch * 128 + 4 * l];
        wr1[cch] = *(const float4*)&W_hh[(size_t)d1 * M_DIM + cch * 128 + 4 * l];
        cw0[cch] = *(const float4*)&C_w [(size_t)d0 * M_DIM + cch * 128 + 4 * l];
        cw1[cch] = *(const float4*)&C_w [(size_t)d1 * M_DIM + cch * 128 + 4 * l];
    }
    const float cb0 = C_b[d0], cb1 = C_b[d1];
    float bh_r = 0.f, bh_z = 0.f, bh_n = 0.f;
    if (w == 0) {
        bh_r = b_hh[dj];
        bh_z = b_hh[M_DIM + dj];
        bh_n = b_hh[2 * M_DIM + dj];
    }

    if (tid < M_DIM) hn_sm[1][tid] = h0[tid];
    __syncthreads();

    float4 nv[4];
    #pragma unroll
    for (int cch = 0; cch < 4; cch++) nv[cch] = *(const float4*)&hn_sm[1][cch * 128 + 4 * l];

    auto chain_sm = [&](const float* __restrict__ row) -> float {
        float acc = 0.f;
        #pragma unroll
        for (int cch = 0; cch < 4; cch++) {
            float4 wv = *(const float4*)&row[cch * 128 + 4 * l];
            acc = fmaf(wv.x, nv[cch].x, fmaf(wv.y, nv[cch].y,
                  fmaf(wv.z, nv[cch].z, fmaf(wv.w, nv[cch].w, acc))));
        }
        return acc;
    };
    auto chain_rg = [&](const float4* wreg) -> float {
        float acc = 0.f;
        #pragma unroll
        for (int cch = 0; cch < 4; cch++) {
            acc = fmaf(wreg[cch].x, nv[cch].x, fmaf(wreg[cch].y, nv[cch].y,
                  fmaf(wreg[cch].z, nv[cch].z, fmaf(wreg[cch].w, nv[cch].w, acc))));
        }
        return acc;
    };
    auto tree = [&](float acc) -> float {
        #pragma unroll
        for (int o = 16; o > 0; o >>= 1) acc += __shfl_xor_sync(0xFFFFFFFFu, acc, o);
        return acc;
    };

    // ---- bootstrap: spec on h0 (verbatim chains), staged to warp 0 ----
    {
        float s0z = tree(chain_sm(&W_sm[(0 * DPC + w)      * M_DIM]));
        float s0n = tree(chain_sm(&W_sm[(1 * DPC + w)      * M_DIM]));
        float s1z = tree(chain_sm(&W_sm[(0 * DPC + 16 + w) * M_DIM]));
        float s1n = tree(chain_sm(&W_sm[(1 * DPC + 16 + w) * M_DIM]));
        float s0r = tree(chain_rg(wr0));
        float s1r = tree(chain_rg(wr1));
        if (l == 0) {
            spec_sm[w]      = make_float4(s0r, s0z, s0n, 0.f);
            spec_sm[16 + w] = make_float4(s1r, s1z, s1n, 0.f);
        }
    }
    __syncthreads();

    float grv = 0.f, gzv = 0.f, gnv = 0.f, hp = 0.f, hnw = 0.f;
    float gir = 0.f, giz = 0.f, gin = 0.f;
    if (w == 0) {
        float4 sp = spec_sm[l];
        grv = sp.x; gzv = sp.y; gnv = sp.z;
        hp  = hn_sm[1][dj];
        gir = __ldg(&d_Gi[dj]);
        giz = __ldg(&d_Gi[M_DIM + dj]);
        gin = __ldg(&d_Gi[2 * M_DIM + dj]);
    }

    int pq = -1, phas = 0, ptb = 0;

    __syncthreads();
    CLUSTER_SYNC();

    for (int t = 0; t < T_STEPS; t++) {
        const int tb = t & 1;
        const unsigned par = (unsigned)(t & 1);
        float ngir = 0.f, ngiz = 0.f, ngin = 0.f;

        // ---------- warp 0: gates + stage + bulk send + Gi prefetch ----------
        if (w == 0) {
            float hr = grv + bh_r, hz = gzv + bh_z, hn = gnv + bh_n;
            float rg = 1.f / (1.f + expf(-(gir + hr)));
            float zg = 1.f / (1.f + expf(-(giz + hz)));
            float ng = tanhf(gin + rg * hn);
            hnw = (1.f - zg) * ng + zg * hp;
            stage_sm[tb][l] = hnw;
            __syncwarp();
            if (l == 0) mbar_expect_tx(&mbar_hn, M_DIM * 4u);
            if (l < CSZ) {
                asm volatile("fence.proxy.async.shared::cta;" ::: "memory");
                bulk_s2s(&hn_sm[tb][DPC * c], &stage_sm[tb][0], &mbar_hn,
                         (unsigned)l, DPC * 4u);
            }
            if (t + 1 < T_STEPS) {
                const float* g = &d_Gi[(size_t)(t + 1) * G3];
                ngir = __ldg(&g[dj]);
                ngiz = __ldg(&g[M_DIM + dj]);
                ngin = __ldg(&g[2 * M_DIM + dj]);
            }
        }

        // ---------- prev-step d_H duty in the hn-flight window ----------
        if (pq >= 0 && c == ((t - 1) & (CSZ - 1))) {
            if (!phas) d_H[(size_t)(t - 1) * M_DIM + tid] = hn_sm[ptb][tid];
            if (tid == 0) d_dec[t - 1] = phas ? pq : -1;
        }

        mbar_wait(&mbar_hn, par);   // all 16 slices landed locally

        // ---------- logits for d0,d1 (all warps) ----------
        #pragma unroll
        for (int cch = 0; cch < 4; cch++) nv[cch] = *(const float4*)&hn_sm[tb][cch * 128 + 4 * l];
        float acc0 = tree(chain_rg(cw0));
        float acc1 = tree(chain_rg(cw1));
        if (l == 0) {
            unsigned int u0 = __float_as_uint(acc0 + cb0);
            u0 ^= (u0 & 0x80000000u) ? 0xFFFFFFFFu : 0x80000000u;
            unsigned long long k0 = ((unsigned long long)u0 << 32) | (unsigned int)(1023 - d0);
            unsigned int u1 = __float_as_uint(acc1 + cb1);
            u1 ^= (u1 & 0x80000000u) ? 0xFFFFFFFFu : 0x80000000u;
            unsigned long long k1 = ((unsigned long long)u1 << 32) | (unsigned int)(1023 - d1);
            wkey_sm[w] = (k0 > k1) ? k0 : k1;
        }
        __syncthreads();
        if (tid == 0) mbar_expect_tx(&mbar_key, CSZ * 8u);
        if (w == 0) {
            unsigned long long best = warp_max_key((l < 16) ? wkey_sm[l] : 0ull);
            if (l < CSZ) stasync_u64(&ckey_sm[c], &mbar_key, (unsigned)l, best);
        }

        mbar_wait(&mbar_key, par);  // all 16 CTA keys landed locally

        // ---------- decision (all threads, REDUX) ----------
        unsigned long long best = warp_max_key((l < CSZ) ? ckey_sm[l] : 0ull);
        const int q   = 1023 - (int)(best & 0xFFFFFFFFull);
        const int has = (q > 0) && (written_w[w][q] != 0);
        __syncwarp();
        if (l == 0 && q > 0) written_w[w][q] = 1;

        if (has) {
            // common case: warp 0 does one coalesced 512B cache read
            if (w == 0) {
                float4 g4 = __ldg(&d_Gc4[(size_t)q * M_DIM + dj]);
                grv = g4.x; gzv = g4.y; gnv = g4.z; hp = g4.w;
            }
        } else {
            // rare: spec GEMV by all warps (verbatim), staged to warp 0
            float s0z = tree(chain_sm(&W_sm[(0 * DPC + w)      * M_DIM]));
            float s0n = tree(chain_sm(&W_sm[(1 * DPC + w)      * M_DIM]));
            float s1z = tree(chain_sm(&W_sm[(0 * DPC + 16 + w) * M_DIM]));
            float s1n = tree(chain_sm(&W_sm[(1 * DPC + 16 + w) * M_DIM]));
            float s0r = tree(chain_rg(wr0));
            float s1r = tree(chain_rg(wr1));
            if (l == 0) {
                spec_sm[w]      = make_float4(s0r, s0z, s0n, 0.f);
                spec_sm[16 + w] = make_float4(s1r, s1z, s1n, 0.f);
            }
            __syncthreads();
            if (w == 0) {
                float4 sp = spec_sm[l];
                grv = sp.x; gzv = sp.y; gnv = sp.z; hp = hnw;
                if (q > 0) {
                    d_Gc4[(size_t)q * M_DIM + dj] = make_float4(grv, gzv, gnv, hp);
                    d_M [(size_t)q * M_DIM + dj]  = hp;
                }
            }
        }
        if (w == 0) { gir = ngir; giz = ngiz; gin = ngin; }

        pq = q; phas = has; ptb = tb;
    }

    if (pq >= 0 && c == ((T_STEPS - 1) & (CSZ - 1))) {
        if (!phas) d_H[(size_t)(T_STEPS - 1) * M_DIM + tid] = hn_sm[ptb][tid];
        if (tid == 0) d_dec[T_STEPS - 1] = phas ? pq : -1;
    }

    CLUSTER_SYNC();
}

extern "C" void kernel_launch(void* const* d_in, const int* in_sizes, int n_in,
                              void* d_out, int out_size)
{
    const float* X    = (const float*)d_in[0];
    const float* h0   = (const float*)d_in[1];
    const float* W_ih = (const float*)d_in[2];
    const float* W_hh = (const float*)d_in[3];
    const float* b_ih = (const float*)d_in[4];
    const float* b_hh = (const float*)d_in[5];
    const float* C_w  = (const float*)d_in[6];
    const float* C_b  = (const float*)d_in[7];
    const float* V_w  = (const float*)d_in[8];
    const float* V_b  = (const float*)d_in[9];
    float* Y = (float*)d_out;

    float* Gi; cudaGetSymbolAddress((void**)&Gi, d_Gi);
    float* H;  cudaGetSymbolAddress((void**)&H,  d_H);

    {
        dim3 blk(32, 32), grid(G3 / 32, T_STEPS / 32);
        gemm32_nt<<<grid, blk>>>(X, W_ih, b_ih, Gi, T_STEPS, G3, N_DIM);
    }
    {
        const int smem = 2 * DPC * M_DIM * (int)sizeof(float);   // 131072
        cudaFuncSetAttribute(dmm_rec, cudaFuncAttributeNonPortableClusterSizeAllowed, 1);
        cudaFuncSetAttribute(dmm_rec, cudaFuncAttributeMaxDynamicSharedMemorySize, smem);
        cudaLaunchConfig_t cfg = {};
        cfg.gridDim  = dim3(CSZ, 1, 1);
        cfg.blockDim = dim3(NTHR, 1, 1);
        cfg.dynamicSmemBytes = smem;
        cfg.stream = 0;
        cudaLaunchAttribute at[1];
        at[0].id = cudaLaunchAttributeClusterDimension;
        at[0].val.clusterDim.x = CSZ;
        at[0].val.clusterDim.y = 1;
        at[0].val.clusterDim.z = 1;
        cfg.attrs = at;
        cfg.numAttrs = 1;
        cudaLaunchKernelEx(&cfg, dmm_rec, h0, W_hh, b_hh, C_w, C_b);
    }
    dmm_fixup<<<T_STEPS, M_DIM>>>();
    {
        dim3 blk(32, 32), grid(L_OUT / 32, T_STEPS / 32);
        gemm32_nt<<<grid, blk>>>(H, V_w, V_b, Y, T_STEPS, L_OUT, M_DIM);
    }
}

// round 15
// speedup vs baseline: 1.1271x; 1.1271x over previous
#include <cuda_runtime.h>
#include <cuda_bf16.h>
#include <math.h>

#define T_STEPS 16384
#define N_DIM   256
#define M_DIM   512
#define G3      1536   // 3*M
#define NADDR   512    // K_MEM+1
#define L_OUT   256

#define CSZ     16     // cluster size (CTAs)
#define DPC     32     // h-dims per CTA (512/16)
#define NTHR    512

// ---------------- device scratch (static, no allocation) ----------------
__device__ __align__(16) float  d_Gi[T_STEPS * G3];      // X @ W_ih^T + b_ih
__device__ __align__(16) float  d_H [T_STEPS * M_DIM];   // h_out history
__device__ __align__(16) float  d_M [NADDR * M_DIM];     // memory rows (write-once)
__device__ __align__(16) float4 d_Gc4[NADDR * M_DIM];    // cache: (gr,gz,gn,hp) per [q][dim]
__device__ int d_dec[T_STEPS];                           // per-step memory-read record

// ---------------- helpers ----------------
__device__ __forceinline__ void stasync_u64(unsigned long long* lptr, unsigned long long* lmbar,
                                            unsigned rank, unsigned long long v) {
    unsigned la = (unsigned)__cvta_generic_to_shared(lptr);
    unsigned lm = (unsigned)__cvta_generic_to_shared(lmbar);
    unsigned ra, rm;
    asm volatile("mapa.shared::cluster.u32 %0, %1, %2;" : "=r"(ra) : "r"(la), "r"(rank));
    asm volatile("mapa.shared::cluster.u32 %0, %1, %2;" : "=r"(rm) : "r"(lm), "r"(rank));
    asm volatile("st.async.weak.shared::cluster.mbarrier::complete_tx::bytes.b64 [%0], %1, [%2];"
                 :: "r"(ra), "l"(v), "r"(rm) : "memory");
}
__device__ __forceinline__ void bulk_s2s(float* ldst, const float* lsrc,
                                         unsigned long long* lmbar,
                                         unsigned rank, unsigned bytes) {
    unsigned ld = (unsigned)__cvta_generic_to_shared(ldst);
    unsigned ls = (unsigned)__cvta_generic_to_shared(lsrc);
    unsigned lm = (unsigned)__cvta_generic_to_shared(lmbar);
    unsigned rd, rm;
    asm volatile("mapa.shared::cluster.u32 %0, %1, %2;" : "=r"(rd) : "r"(ld), "r"(rank));
    asm volatile("mapa.shared::cluster.u32 %0, %1, %2;" : "=r"(rm) : "r"(lm), "r"(rank));
    asm volatile("cp.async.bulk.shared::cluster.shared::cta.mbarrier::complete_tx::bytes "
                 "[%0], [%1], %2, [%3];"
                 :: "r"(rd), "r"(ls), "r"(bytes), "r"(rm) : "memory");
}
__device__ __forceinline__ void mbar_init(unsigned long long* m, unsigned cnt) {
    unsigned a = (unsigned)__cvta_generic_to_shared(m);
    asm volatile("mbarrier.init.shared.b64 [%0], %1;" :: "r"(a), "r"(cnt) : "memory");
}
__device__ __forceinline__ void mbar_expect_tx(unsigned long long* m, unsigned bytes) {
    unsigned a = (unsigned)__cvta_generic_to_shared(m);
    asm volatile("mbarrier.arrive.expect_tx.shared.b64 _, [%0], %1;" :: "r"(a), "r"(bytes) : "memory");
}
__device__ __forceinline__ void mbar_wait(unsigned long long* m, unsigned parity) {
    unsigned a = (unsigned)__cvta_generic_to_shared(m);
    unsigned done;
    asm volatile("{\n\t.reg .pred p;\n\t"
                 "mbarrier.try_wait.parity.acquire.cta.shared::cta.b64 p, [%1], %2;\n\t"
                 "selp.b32 %0, 1, 0, p;\n\t}"
                 : "=r"(done) : "r"(a), "r"(parity) : "memory");
    if (!done) {
        asm volatile("{\n\t.reg .pred P1;\n\t"
                     "WL_%=:\n\t"
                     "mbarrier.try_wait.parity.acquire.cta.shared::cta.b64 P1, [%0], %1, 0x989680;\n\t"
                     "@P1 bra.uni WD_%=;\n\t"
                     "bra.uni WL_%=;\n\t"
                     "WD_%=:\n\t}"
                     :: "r"(a), "r"(parity) : "memory");
    }
}
#define CLUSTER_SYNC() do { \
    asm volatile("barrier.cluster.arrive.aligned;" ::: "memory"); \
    asm volatile("barrier.cluster.wait.aligned;"   ::: "memory"); } while (0)

__device__ __forceinline__ unsigned long long warp_max_key(unsigned long long k) {
    unsigned hi = (unsigned)(k >> 32);
    unsigned lo = (unsigned)k;
    unsigned mhi = __reduce_max_sync(0xFFFFFFFFu, hi);
    unsigned mlo = __reduce_max_sync(0xFFFFFFFFu, (hi == mhi) ? lo : 0u);
    return ((unsigned long long)mhi << 32) | mlo;
}

// ---------------- textbook 32x32 tiled NT GEMM (known good) ----------------
__global__ __launch_bounds__(1024) void gemm32_nt(
    const float* __restrict__ A, const float* __restrict__ B,
    const float* __restrict__ bias, float* __restrict__ C,
    int M, int N, int K)
{
    __shared__ float As[32][33];
    __shared__ float Bs[32][33];
    const int bm = blockIdx.y * 32;
    const int bn = blockIdx.x * 32;
    const int tx = threadIdx.x;
    const int ty = threadIdx.y;
    float acc = 0.f;
    for (int k0 = 0; k0 < K; k0 += 32) {
        As[ty][tx] = A[(size_t)(bm + ty) * K + k0 + tx];
        Bs[ty][tx] = B[(size_t)(bn + ty) * K + k0 + tx];
        __syncthreads();
        #pragma unroll
        for (int k = 0; k < 32; k++)
            acc = fmaf(As[ty][k], Bs[tx][k], acc);
        __syncthreads();
    }
    C[(size_t)(bm + ty) * N + bn + tx] = acc + bias[bn + tx];
}

// ---------------- post-pass: fill d_H rows recorded as memory reads ----------------
__global__ __launch_bounds__(M_DIM) void dmm_fixup(void) {
    const int t = blockIdx.x;
    const int q = d_dec[t];
    if (q >= 0)
        d_H[(size_t)t * M_DIM + threadIdx.x] = d_M[(size_t)q * M_DIM + threadIdx.x];
}

// ---------------- clustered recurrent kernel ----------------
// Round-13 structure (distributed gates, conditional speculation) + split hn
// mbarriers (A: ranks 0-7, B: ranks 8-15) so logit chain chunks 0-1 overlap
// the tail of the DSMEM flight, + early key expect_tx. Per-value arithmetic
// verbatim -> trajectory bit-identical to rounds 4..13.
__global__ __launch_bounds__(NTHR, 1) void dmm_rec(
    const float* __restrict__ h0,
    const float* __restrict__ W_hh,
    const float* __restrict__ b_hh,
    const float* __restrict__ C_w,
    const float* __restrict__ C_b)
{
    extern __shared__ float W_sm[];                 // [2*DPC][512]: z rows, n rows
    __shared__ __align__(16) float hn_sm[2][M_DIM];
    __shared__ __align__(16) float stage_sm[2][DPC];
    __shared__ unsigned long long wkey_sm[16];
    __shared__ unsigned long long ckey_sm[CSZ];
    __shared__ unsigned char written_w[16][NADDR];
    __shared__ unsigned long long mbar_hnA, mbar_hnB, mbar_key;

    const int c   = blockIdx.x;
    const int tid = threadIdx.x;
    const int w   = tid >> 5;
    const int l   = tid & 31;
    const int ml  = l & 15;
    const int d0  = DPC * c + w;
    const int d1  = DPC * c + 16 + w;
    const int myd = (l < 16) ? d0 : d1;

    for (int idx = tid; idx < 2 * DPC * M_DIM; idx += NTHR) {
        int g   = idx >> 14;
        int rem = idx & 16383;
        int lr  = rem >> 9;
        int col = rem & 511;
        W_sm[idx] = W_hh[(size_t)((g + 1) * M_DIM + DPC * c + lr) * M_DIM + col];
    }
    for (int idx = tid; idx < 16 * NADDR; idx += NTHR)
        written_w[idx >> 9][idx & 511] = 0;
    if (tid == 0) {
        mbar_init(&mbar_hnA, 1);
        mbar_init(&mbar_hnB, 1);
        mbar_init(&mbar_key, 1);
        asm volatile("fence.mbarrier_init.release.cluster;" ::: "memory");
    }

    float4 wr0[4], wr1[4], cw0[4], cw1[4];
    #pragma unroll
    for (int cch = 0; cch < 4; cch++) {
        wr0[cch] = *(const float4*)&W_hh[(size_t)d0 * M_DIM + cch * 128 + 4 * l];
        wr1[cch] = *(const float4*)&W_hh[(size_t)d1 * M_DIM + cch * 128 + 4 * l];
        cw0[cch] = *(const float4*)&C_w [(size_t)d0 * M_DIM + cch * 128 + 4 * l];
        cw1[cch] = *(const float4*)&C_w [(size_t)d1 * M_DIM + cch * 128 + 4 * l];
    }
    const float cb0 = C_b[d0], cb1 = C_b[d1];
    const float bhr = b_hh[myd], bhz = b_hh[M_DIM + myd], bhn = b_hh[2 * M_DIM + myd];

    if (tid < M_DIM) hn_sm[1][tid] = h0[tid];
    __syncthreads();

    float4 nv[4];
    #pragma unroll
    for (int cch = 0; cch < 4; cch++) nv[cch] = *(const float4*)&hn_sm[1][cch * 128 + 4 * l];

    auto chain_sm = [&](const float* __restrict__ row) -> float {
        float acc = 0.f;
        #pragma unroll
        for (int cch = 0; cch < 4; cch++) {
            float4 wv = *(const float4*)&row[cch * 128 + 4 * l];
            acc = fmaf(wv.x, nv[cch].x, fmaf(wv.y, nv[cch].y,
                  fmaf(wv.z, nv[cch].z, fmaf(wv.w, nv[cch].w, acc))));
        }
        return acc;
    };
    auto chain_rg = [&](const float4* wreg) -> float {
        float acc = 0.f;
        #pragma unroll
        for (int cch = 0; cch < 4; cch++) {
            acc = fmaf(wreg[cch].x, nv[cch].x, fmaf(wreg[cch].y, nv[cch].y,
                  fmaf(wreg[cch].z, nv[cch].z, fmaf(wreg[cch].w, nv[cch].w, acc))));
        }
        return acc;
    };
    // partial chain over chunks [c0, c1) continuing from acc (same op order)
    auto chain_rg_part = [&](const float4* wreg, float acc, int c0, int c1) -> float {
        for (int cch = c0; cch < c1; cch++) {
            acc = fmaf(wreg[cch].x, nv[cch].x, fmaf(wreg[cch].y, nv[cch].y,
                  fmaf(wreg[cch].z, nv[cch].z, fmaf(wreg[cch].w, nv[cch].w, acc))));
        }
        return acc;
    };
    auto tree = [&](float acc) -> float {
        #pragma unroll
        for (int o = 16; o > 0; o >>= 1) acc += __shfl_xor_sync(0xFFFFFFFFu, acc, o);
        return acc;
    };

    // persistent gate inputs (bootstrap = spec on h0, verbatim chains)
    float grv, gzv, gnv;
    {
        float s0z = tree(chain_sm(&W_sm[(0 * DPC + w)      * M_DIM]));
        float s0n = tree(chain_sm(&W_sm[(1 * DPC + w)      * M_DIM]));
        float s1z = tree(chain_sm(&W_sm[(0 * DPC + 16 + w) * M_DIM]));
        float s1n = tree(chain_sm(&W_sm[(1 * DPC + 16 + w) * M_DIM]));
        float s0r = tree(chain_rg(wr0));
        float s1r = tree(chain_rg(wr1));
        grv = (l < 16) ? s0r : s1r;
        gzv = (l < 16) ? s0z : s1z;
        gnv = (l < 16) ? s0n : s1n;
    }
    float hp = hn_sm[1][myd];
    float gir = 0.f, giz = 0.f, gin = 0.f;
    if (ml == 0) {
        gir = __ldg(&d_Gi[myd]);
        giz = __ldg(&d_Gi[M_DIM + myd]);
        gin = __ldg(&d_Gi[2 * M_DIM + myd]);
    }

    int pq = -1, phas = 0, ptb = 0;

    __syncthreads();
    CLUSTER_SYNC();

    for (int t = 0; t < T_STEPS; t++) {
        const int tb = t & 1;
        const unsigned par = (unsigned)(t & 1);

        float hnewv = 0.f;
        if (ml == 0) {
            float hr = grv + bhr, hz = gzv + bhz, hn = gnv + bhn;
            float rg = 1.f / (1.f + expf(-(gir + hr)));
            float zg = 1.f / (1.f + expf(-(giz + hz)));
            float ng = tanhf(gin + rg * hn);
            hnewv = (1.f - zg) * ng + zg * hp;
            stage_sm[tb][w + ((l < 16) ? 0 : 16)] = hnewv;
        }
        const float v0 = __shfl_sync(0xFFFFFFFFu, hnewv, 0);
        const float v1 = __shfl_sync(0xFFFFFFFFu, hnewv, 16);
        __syncthreads();

        if (tid == 0) {
            mbar_expect_tx(&mbar_hnA, 8 * DPC * 4u);   // 1024 B from ranks 0-7
            mbar_expect_tx(&mbar_hnB, 8 * DPC * 4u);   // 1024 B from ranks 8-15
            mbar_expect_tx(&mbar_key, CSZ * 8u);       // early: key phase accounting
        }
        if (w == 0 && l < CSZ) {
            asm volatile("fence.proxy.async.shared::cta;" ::: "memory");
            // sender rank c chooses the receiver-side barrier by its own rank
            bulk_s2s(&hn_sm[tb][DPC * c], &stage_sm[tb][0],
                     (c < 8) ? &mbar_hnA : &mbar_hnB,
                     (unsigned)l, DPC * 4u);
        }

        if (pq >= 0 && c == ((t - 1) & (CSZ - 1))) {
            if (!phas) d_H[(size_t)(t - 1) * M_DIM + tid] = hn_sm[ptb][tid];
            if (tid == 0) d_dec[t - 1] = phas ? pq : -1;
        }
        float ngir = 0.f, ngiz = 0.f, ngin = 0.f;
        if (ml == 0 && t + 1 < T_STEPS) {
            const float* g = &d_Gi[(size_t)(t + 1) * G3];
            ngir = __ldg(&g[myd]);
            ngiz = __ldg(&g[M_DIM + myd]);
            ngin = __ldg(&g[2 * M_DIM + myd]);
        }

        // ---------- staged hn arrival: chunks 0-1 overlap ranks 8-15 flight ----------
        mbar_wait(&mbar_hnA, par);   // dims [0,256) present
        nv[0] = *(const float4*)&hn_sm[tb][0 * 128 + 4 * l];
        nv[1] = *(const float4*)&hn_sm[tb][1 * 128 + 4 * l];
        float acc0 = chain_rg_part(cw0, 0.f, 0, 2);
        float acc1 = chain_rg_part(cw1, 0.f, 0, 2);
        mbar_wait(&mbar_hnB, par);   // dims [256,512) present
        nv[2] = *(const float4*)&hn_sm[tb][2 * 128 + 4 * l];
        nv[3] = *(const float4*)&hn_sm[tb][3 * 128 + 4 * l];
        acc0 = tree(chain_rg_part(cw0, acc0, 2, 4));
        acc1 = tree(chain_rg_part(cw1, acc1, 2, 4));

        if (l == 0) {
            unsigned int u0 = __float_as_uint(acc0 + cb0);
            u0 ^= (u0 & 0x80000000u) ? 0xFFFFFFFFu : 0x80000000u;
            unsigned long long k0 = ((unsigned long long)u0 << 32) | (unsigned int)(1023 - d0);
            unsigned int u1 = __float_as_uint(acc1 + cb1);
            u1 ^= (u1 & 0x80000000u) ? 0xFFFFFFFFu : 0x80000000u;
            unsigned long long k1 = ((unsigned long long)u1 << 32) | (unsigned int)(1023 - d1);
            wkey_sm[w] = (k0 > k1) ? k0 : k1;
        }
        __syncthreads();
        if (w == 0) {
            unsigned long long best = warp_max_key((l < 16) ? wkey_sm[l] : 0ull);
            if (l < CSZ) stasync_u64(&ckey_sm[c], &mbar_key, (unsigned)l, best);
        }

        mbar_wait(&mbar_key, par);

        unsigned long long best = warp_max_key((l < CSZ) ? ckey_sm[l] : 0ull);
        const int q   = 1023 - (int)(best & 0xFFFFFFFFull);
        const int has = (q > 0) && (written_w[w][q] != 0);
        __syncwarp();
        if (l == 0 && q > 0) written_w[w][q] = 1;

        const float hnw = (l < 16) ? v0 : v1;

        if (has) {
            if (ml == 0) {
                float4 g4 = __ldg(&d_Gc4[(size_t)q * M_DIM + myd]);
                grv = g4.x; gzv = g4.y; gnv = g4.z; hp = g4.w;
            }
        } else {
            float s0z = tree(chain_sm(&W_sm[(0 * DPC + w)      * M_DIM]));
            float s0n = tree(chain_sm(&W_sm[(1 * DPC + w)      * M_DIM]));
            float s1z = tree(chain_sm(&W_sm[(0 * DPC + 16 + w) * M_DIM]));
            float s1n = tree(chain_sm(&W_sm[(1 * DPC + 16 + w) * M_DIM]));
            float s0r = tree(chain_rg(wr0));
            float s1r = tree(chain_rg(wr1));
            const float s_r = (l < 16) ? s0r : s1r;
            const float s_z = (l < 16) ? s0z : s1z;
            const float s_n = (l < 16) ? s0n : s1n;
            if (ml == 0) {
                grv = s_r; gzv = s_z; gnv = s_n; hp = hnw;
                if (q > 0) {
                    d_Gc4[(size_t)q * M_DIM + myd] = make_float4(s_r, s_z, s_n, hnw);
                    d_M [(size_t)q * M_DIM + myd]  = hnw;
                }
            }
        }
        if (ml == 0) { gir = ngir; giz = ngiz; gin = ngin; }

        pq = q; phas = has; ptb = tb;
    }

    if (pq >= 0 && c == ((T_STEPS - 1) & (CSZ - 1))) {
        if (!phas) d_H[(size_t)(T_STEPS - 1) * M_DIM + tid] = hn_sm[ptb][tid];
        if (tid == 0) d_dec[T_STEPS - 1] = phas ? pq : -1;
    }

    CLUSTER_SYNC();
}

extern "C" void kernel_launch(void* const* d_in, const int* in_sizes, int n_in,
                              void* d_out, int out_size)
{
    const float* X    = (const float*)d_in[0];
    const float* h0   = (const float*)d_in[1];
    const float* W_ih = (const float*)d_in[2];
    const float* W_hh = (const float*)d_in[3];
    const float* b_ih = (const float*)d_in[4];
    const float* b_hh = (const float*)d_in[5];
    const float* C_w  = (const float*)d_in[6];
    const float* C_b  = (const float*)d_in[7];
    const float* V_w  = (const float*)d_in[8];
    const float* V_b  = (const float*)d_in[9];
    float* Y = (float*)d_out;

    float* Gi; cudaGetSymbolAddress((void**)&Gi, d_Gi);
    float* H;  cudaGetSymbolAddress((void**)&H,  d_H);

    {
        dim3 blk(32, 32), grid(G3 / 32, T_STEPS / 32);
        gemm32_nt<<<grid, blk>>>(X, W_ih, b_ih, Gi, T_STEPS, G3, N_DIM);
    }
    {
        const int smem = 2 * DPC * M_DIM * (int)sizeof(float);   // 131072
        cudaFuncSetAttribute(dmm_rec, cudaFuncAttributeNonPortableClusterSizeAllowed, 1);
        cudaFuncSetAttribute(dmm_rec, cudaFuncAttributeMaxDynamicSharedMemorySize, smem);
        cudaLaunchConfig_t cfg = {};
        cfg.gridDim  = dim3(CSZ, 1, 1);
        cfg.blockDim = dim3(NTHR, 1, 1);
        cfg.dynamicSmemBytes = smem;
        cfg.stream = 0;
        cudaLaunchAttribute at[1];
        at[0].id = cudaLaunchAttributeClusterDimension;
        at[0].val.clusterDim.x = CSZ;
        at[0].val.clusterDim.y = 1;
        at[0].val.clusterDim.z = 1;
        cfg.attrs = at;
        cfg.numAttrs = 1;
        cudaLaunchKernelEx(&cfg, dmm_rec, h0, W_hh, b_hh, C_w, C_b);
    }
    dmm_fixup<<<T_STEPS, M_DIM>>>();
    {
        dim3 blk(32, 32), grid(L_OUT / 32, T_STEPS / 32);
        gemm32_nt<<<grid, blk>>>(H, V_w, V_b, Y, T_STEPS, L_OUT, M_DIM);
    }
}